// round 7
// baseline (speedup 1.0000x reference)
#include <cuda_runtime.h>
#include <math.h>
#include <math_constants.h>
#include <stdint.h>

#define BB 8
#define SS 2500
#define EE 128
#define FF 128
#define LL 8921

// ---------------- device scratch (no allocations allowed) ----------------
__device__ __align__(16) float g_wp3[3 * EE * FF];
__device__ __align__(16) float g_wp5[5 * EE * FF];
__device__ __align__(16) float g_wp9[9 * EE * FF];
// +64 pad: cp.async tile loads over-read the last row tail; pad keeps them in-bounds
__device__ __align__(16) float g_wf[(size_t)BB * FF * SS + 64];
__device__ float g_y_fb[BB * LL];
__device__ float g_ctx_fb[(size_t)BB * LL * FF];

__device__ __forceinline__ uint32_t f2tf32(float v) {
    uint32_t t;
    asm("cvt.rna.tf32.f32 %0, %1;" : "=r"(t) : "f"(v));
    return t;
}

// ---------------- merged weight repack: [F][E][K] -> [K][E][F] x3 ----------------
__global__ void repack_all_kernel(const float* __restrict__ w3,
                                  const float* __restrict__ w5,
                                  const float* __restrict__ w9,
                                  float* __restrict__ p3,
                                  float* __restrict__ p5,
                                  float* __restrict__ p9) {
    const int n3 = 3 * EE * FF, n5 = 5 * EE * FF, n9 = 9 * EE * FF;
    int idx = blockIdx.x * blockDim.x + threadIdx.x;
    const float* src; float* dst; int K; int loc;
    if (idx < n3)           { src = w3; dst = p3; K = 3; loc = idx; }
    else if (idx < n3 + n5) { src = w5; dst = p5; K = 5; loc = idx - n3; }
    else if (idx < n3 + n5 + n9) { src = w9; dst = p9; K = 9; loc = idx - n3 - n5; }
    else return;
    int kk = loc / (EE * FF);
    int r  = loc % (EE * FF);
    int e  = r / FF;
    int f  = r % FF;
    dst[loc] = src[(f * EE + e) * K + kk];
}

// ================= conv: 4f x 8s per thread, register xs window =================
#define CTILE 64
#define XSTR  72

template <int K>
__device__ __forceinline__ void conv_max2(const float* __restrict__ wp,
                                          const float* __restrict__ bias,
                                          const float (*xs)[XSTR],
                                          int f0, int sg, float mx[4][8]) {
    float acc[4][8];
#pragma unroll
    for (int i = 0; i < 4; i++)
#pragma unroll
        for (int j = 0; j < 8; j++) acc[i][j] = 0.f;

    const int P = K / 2;
    const int w0 = 8 * sg;
#pragma unroll 2
    for (int e = 0; e < EE; e++) {
        float xw[16];
        const float4* xr = (const float4*)(&xs[e][w0]);
        float4 xa = xr[0], xb = xr[1], xc = xr[2], xd = xr[3];
        xw[0]=xa.x; xw[1]=xa.y; xw[2]=xa.z; xw[3]=xa.w;
        xw[4]=xb.x; xw[5]=xb.y; xw[6]=xb.z; xw[7]=xb.w;
        xw[8]=xc.x; xw[9]=xc.y; xw[10]=xc.z; xw[11]=xc.w;
        xw[12]=xd.x; xw[13]=xd.y; xw[14]=xd.z; xw[15]=xd.w;
#pragma unroll
        for (int kk = 0; kk < K; kk++) {
            float4 wv = *(const float4*)(wp + (kk * EE + e) * FF + f0);
            const int off = 4 + kk - P;
#pragma unroll
            for (int j = 0; j < 8; j++) {
                float x = xw[off + j];
                acc[0][j] += wv.x * x;
                acc[1][j] += wv.y * x;
                acc[2][j] += wv.z * x;
                acc[3][j] += wv.w * x;
            }
        }
    }
#pragma unroll
    for (int i = 0; i < 4; i++) {
        float bi = bias[f0 + i];
#pragma unroll
        for (int j = 0; j < 8; j++)
            mx[i][j] = fmaxf(mx[i][j], tanhf(acc[i][j] + bi));
    }
}

__global__ __launch_bounds__(256, 2) void conv_kernel(
    const int* __restrict__ docs, const float* __restrict__ embed,
    const float* __restrict__ b3, const float* __restrict__ b5,
    const float* __restrict__ b9) {
    __shared__ float xs[EE][XSTR];

    int b  = blockIdx.y;
    int s0 = blockIdx.x * CTILE;
    int tid = threadIdx.x, w = tid >> 5, lane = tid & 31;

#pragma unroll
    for (int q = 0; q < 9; q++) {
        int p = w * 9 + q;
        int s = s0 - 4 + p;
        if (s >= 0 && s < SS) {
            int tok = docs[b * SS + s];
            const float* er = embed + (size_t)tok * EE;
            xs[lane      ][p] = er[lane];
            xs[lane + 32][p] = er[lane + 32];
            xs[lane + 64][p] = er[lane + 64];
            xs[lane + 96][p] = er[lane + 96];
        } else {
            xs[lane][p] = 0.f; xs[lane + 32][p] = 0.f;
            xs[lane + 64][p] = 0.f; xs[lane + 96][p] = 0.f;
        }
    }
    __syncthreads();

    int fg = tid >> 3;
    int sg = tid & 7;
    int f0 = fg * 4;

    float mx[4][8];
#pragma unroll
    for (int i = 0; i < 4; i++)
#pragma unroll
        for (int j = 0; j < 8; j++) mx[i][j] = -1e30f;

    conv_max2<3>(g_wp3, b3, xs, f0, sg, mx);
    conv_max2<5>(g_wp5, b5, xs, f0, sg, mx);
    conv_max2<9>(g_wp9, b9, xs, f0, sg, mx);

    // store tf32-RNA-rounded word features: later HMMA truncation is then exact
#pragma unroll
    for (int i = 0; i < 4; i++) {
        float* orow = g_wf + ((size_t)b * FF + f0 + i) * SS;
#pragma unroll
        for (int j = 0; j < 8; j++) {
            int s = s0 + 8 * sg + j;
            if (s < SS) orow[s] = __uint_as_float(f2tf32(mx[i][j]));
        }
    }
}

// ================= tensor-core label attention v3 (64-wide S tiles) =================
#define LBLK 64
#define X_STRIDE  68
#define P_STRIDE  68
#define STILE     64
#define NT_TILES  ((SS + STILE - 1) / STILE)   // 40

__device__ __forceinline__ void mma_tf32(float (&d)[4],
                                         uint32_t a0, uint32_t a1,
                                         uint32_t a2, uint32_t a3,
                                         uint32_t b0, uint32_t b1) {
    asm volatile(
        "mma.sync.aligned.m16n8k8.row.col.f32.tf32.tf32.f32 "
        "{%0,%1,%2,%3}, {%4,%5,%6,%7}, {%8,%9}, {%0,%1,%2,%3};"
        : "+f"(d[0]), "+f"(d[1]), "+f"(d[2]), "+f"(d[3])
        : "r"(a0), "r"(a1), "r"(a2), "r"(a3), "r"(b0), "r"(b1));
}

__device__ __forceinline__ void ldx_async(float* s_buf, const float* wfb,
                                          int s0, int tid) {
#pragma unroll
    for (int v = 0; v < 16; v++) {
        int lin = v * 128 + tid;
        int f = lin >> 4, c = lin & 15;
        uint32_t dst = (uint32_t)__cvta_generic_to_shared(s_buf + f * X_STRIDE + c * 4);
        const float* src = wfb + (size_t)f * SS + s0 + c * 4;
        asm volatile("cp.async.ca.shared.global [%0], [%1], 16;"
                     :: "r"(dst), "l"(src));
    }
}

__global__ __launch_bounds__(128, 2) void attn_tc_kernel(
    const float* __restrict__ wu_w, const int* __restrict__ leaf,
    const float* __restrict__ fw, const float* __restrict__ fb,
    float* __restrict__ y_out, float* __restrict__ ctx_out) {
    extern __shared__ float sm[];
    float* s_x0 = sm;                               // [128][68]
    float* s_x1 = sm + FF * X_STRIDE;               // [128][68]
    float* s_p  = s_x1 + FF * X_STRIDE;             // [4][16][68]

    int b   = blockIdx.y;
    int l0  = blockIdx.x * LBLK;
    int tid = threadIdx.x;
    int wid = tid >> 5, lane = tid & 31;
    int q = lane & 3;
    int r = lane >> 2;

    const int lrow = 16 * wid + r;
    int gl0 = l0 + lrow, gl1 = gl0 + 8;
    bool v0 = gl0 < LL, v1 = gl1 < LL;

    // WU A-fragments in registers for the whole loop
    const float* wr0 = wu_w + (size_t)(v0 ? leaf[gl0] : 0) * FF;
    const float* wr1 = wu_w + (size_t)(v1 ? leaf[gl1] : 0) * FF;
    uint32_t wua[16][4];
#pragma unroll
    for (int k = 0; k < 16; k++) {
        wua[k][0] = v0 ? f2tf32(wr0[8 * k + q])     : 0u;
        wua[k][1] = v1 ? f2tf32(wr1[8 * k + q])     : 0u;
        wua[k][2] = v0 ? f2tf32(wr0[8 * k + q + 4]) : 0u;
        wua[k][3] = v1 ? f2tf32(wr1[8 * k + q + 4]) : 0u;
    }

    const float* wfb = g_wf + (size_t)b * FF * SS;
    float* s_pw = s_p + wid * 16 * P_STRIDE;

    float ctx[16][4];
#pragma unroll
    for (int nt = 0; nt < 16; nt++)
#pragma unroll
        for (int c = 0; c < 4; c++) ctx[nt][c] = 0.f;

    float m0 = -CUDART_INF_F, m1 = -CUDART_INF_F;
    float se0 = 0.f, se1 = 0.f;

    ldx_async(s_x0, wfb, 0, tid);
    asm volatile("cp.async.commit_group;");

    for (int t = 0; t < NT_TILES; t++) {
        int s0 = t * STILE;
        float* xb = (t & 1) ? s_x1 : s_x0;
        if (t + 1 < NT_TILES) {
            ldx_async((t & 1) ? s_x0 : s_x1, wfb, s0 + STILE, tid);
            asm volatile("cp.async.commit_group;");
            asm volatile("cp.async.wait_group 1;");
        } else {
            asm volatile("cp.async.wait_group 0;");
        }
        __syncthreads();

        // ---- GEMM1: scores [16 x 64] ----
        float sc[8][4];
#pragma unroll
        for (int nt = 0; nt < 8; nt++)
#pragma unroll
            for (int c = 0; c < 4; c++) sc[nt][c] = 0.f;

#pragma unroll 2
        for (int k = 0; k < 16; k++) {
            int k0 = 8 * k;
#pragma unroll
            for (int nt = 0; nt < 8; nt++) {
                uint32_t b0 = __float_as_uint(xb[(k0 + q) * X_STRIDE + 8 * nt + r]);
                uint32_t b1 = __float_as_uint(xb[(k0 + q + 4) * X_STRIDE + 8 * nt + r]);
                mma_tf32(sc[nt], wua[k][0], wua[k][1], wua[k][2], wua[k][3], b0, b1);
            }
        }

        // ---- mask tail columns ----
#pragma unroll
        for (int nt = 0; nt < 8; nt++) {
            int s_even = s0 + 8 * nt + 2 * q;
            if (s_even >= SS)     { sc[nt][0] = -CUDART_INF_F; sc[nt][2] = -CUDART_INF_F; }
            if (s_even + 1 >= SS) { sc[nt][1] = -CUDART_INF_F; sc[nt][3] = -CUDART_INF_F; }
        }

        // ---- online softmax over 64 columns ----
        float mx0 = -CUDART_INF_F, mx1 = -CUDART_INF_F;
#pragma unroll
        for (int nt = 0; nt < 8; nt++) {
            mx0 = fmaxf(mx0, fmaxf(sc[nt][0], sc[nt][1]));
            mx1 = fmaxf(mx1, fmaxf(sc[nt][2], sc[nt][3]));
        }
        mx0 = fmaxf(mx0, __shfl_xor_sync(0xffffffffu, mx0, 1));
        mx0 = fmaxf(mx0, __shfl_xor_sync(0xffffffffu, mx0, 2));
        mx1 = fmaxf(mx1, __shfl_xor_sync(0xffffffffu, mx1, 1));
        mx1 = fmaxf(mx1, __shfl_xor_sync(0xffffffffu, mx1, 2));

        float nm0 = fmaxf(m0, mx0), nm1 = fmaxf(m1, mx1);
        float scale0 = __expf(m0 - nm0), scale1 = __expf(m1 - nm1);
        m0 = nm0; m1 = nm1;

        float sum0 = 0.f, sum1 = 0.f;
#pragma unroll
        for (int nt = 0; nt < 8; nt++) {
            float p0 = __expf(sc[nt][0] - m0);
            float p1 = __expf(sc[nt][1] - m0);
            float p2 = __expf(sc[nt][2] - m1);
            float p3 = __expf(sc[nt][3] - m1);
            sum0 += p0 + p1;
            sum1 += p2 + p3;
            int col = 8 * nt + 2 * q;
            s_pw[r * P_STRIDE + col]           = __uint_as_float(f2tf32(p0));
            s_pw[r * P_STRIDE + col + 1]       = __uint_as_float(f2tf32(p1));
            s_pw[(r + 8) * P_STRIDE + col]     = __uint_as_float(f2tf32(p2));
            s_pw[(r + 8) * P_STRIDE + col + 1] = __uint_as_float(f2tf32(p3));
        }
        sum0 += __shfl_xor_sync(0xffffffffu, sum0, 1);
        sum0 += __shfl_xor_sync(0xffffffffu, sum0, 2);
        sum1 += __shfl_xor_sync(0xffffffffu, sum1, 1);
        sum1 += __shfl_xor_sync(0xffffffffu, sum1, 2);
        se0 = se0 * scale0 + sum0;
        se1 = se1 * scale1 + sum1;

#pragma unroll
        for (int nt = 0; nt < 16; nt++) {
            ctx[nt][0] *= scale0; ctx[nt][1] *= scale0;
            ctx[nt][2] *= scale1; ctx[nt][3] *= scale1;
        }
        __syncwarp();

        // ---- GEMM2: ctx += P[16x64] @ X^T[64x128] ----
#pragma unroll
        for (int k = 0; k < 8; k++) {
            int k0 = 8 * k;
            uint32_t a0 = __float_as_uint(s_pw[r * P_STRIDE + k0 + q]);
            uint32_t a1 = __float_as_uint(s_pw[(r + 8) * P_STRIDE + k0 + q]);
            uint32_t a2 = __float_as_uint(s_pw[r * P_STRIDE + k0 + q + 4]);
            uint32_t a3 = __float_as_uint(s_pw[(r + 8) * P_STRIDE + k0 + q + 4]);
#pragma unroll
            for (int nt = 0; nt < 16; nt++) {
                uint32_t b0 = __float_as_uint(xb[(8 * nt + r) * X_STRIDE + k0 + q]);
                uint32_t b1 = __float_as_uint(xb[(8 * nt + r) * X_STRIDE + k0 + q + 4]);
                mma_tf32(ctx[nt], a0, a1, a2, a3, b0, b1);
            }
        }
        __syncthreads();
    }

    // ---- epilogue ----
    float inv0 = 1.f / se0, inv1 = 1.f / se1;
    size_t cb0 = ((size_t)b * LL + gl0) * FF;
    size_t cb1 = ((size_t)b * LL + gl1) * FF;
    float y0 = 0.f, y1 = 0.f;
#pragma unroll
    for (int nt = 0; nt < 16; nt++) {
        int f = 8 * nt + 2 * q;
        if (v0) {
            float c0 = ctx[nt][0] * inv0, c1 = ctx[nt][1] * inv0;
            float2 fwv = *(const float2*)(fw + (size_t)gl0 * FF + f);
            *(float2*)(ctx_out + cb0 + f) = make_float2(c0, c1);
            y0 += c0 * fwv.x + c1 * fwv.y;
        }
        if (v1) {
            float c2 = ctx[nt][2] * inv1, c3 = ctx[nt][3] * inv1;
            float2 fwv = *(const float2*)(fw + (size_t)gl1 * FF + f);
            *(float2*)(ctx_out + cb1 + f) = make_float2(c2, c3);
            y1 += c2 * fwv.x + c3 * fwv.y;
        }
    }
    y0 += __shfl_xor_sync(0xffffffffu, y0, 1);
    y0 += __shfl_xor_sync(0xffffffffu, y0, 2);
    y1 += __shfl_xor_sync(0xffffffffu, y1, 1);
    y1 += __shfl_xor_sync(0xffffffffu, y1, 2);
    if (q == 0 && v0) y_out[(size_t)b * LL + gl0] = y0 + fb[gl0];
    if (q == 0 && v1) y_out[(size_t)b * LL + gl1] = y1 + fb[gl1];
}

// ---------------- launch ----------------
extern "C" void kernel_launch(void* const* d_in, const int* in_sizes, int n_in,
                              void* d_out, int out_size) {
    const int*   docs  = (const int*)  d_in[0];
    const int*   leaf  = (const int*)  d_in[3];
    const float* embed = (const float*)d_in[4];
    const float* wu    = (const float*)d_in[5];
    const float* fw    = (const float*)d_in[6];
    const float* fb    = (const float*)d_in[7];
    const float* w3    = (const float*)d_in[8];
    const float* b3    = (const float*)d_in[9];
    const float* w5    = (const float*)d_in[10];
    const float* b5    = (const float*)d_in[11];
    const float* w9    = (const float*)d_in[12];
    const float* b9    = (const float*)d_in[13];

    const long long NY = (long long)BB * LL;
    const long long NC = (long long)BB * LL * FF;
    float* out = (float*)d_out;
    float* d_y;
    float* d_ctx;
    if ((long long)out_size == NY + NC) {
        d_y = out; d_ctx = out + NY;
    } else if ((long long)out_size == NC) {
        d_ctx = out;
        cudaGetSymbolAddress((void**)&d_y, g_y_fb);
    } else if ((long long)out_size == NY) {
        d_y = out;
        cudaGetSymbolAddress((void**)&d_ctx, g_ctx_fb);
    } else {
        d_y = out; d_ctx = out + NY;
    }

    float* wp3; float* wp5; float* wp9;
    cudaGetSymbolAddress((void**)&wp3, g_wp3);
    cudaGetSymbolAddress((void**)&wp5, g_wp5);
    cudaGetSymbolAddress((void**)&wp9, g_wp9);

    const int nrep = 17 * EE * FF;
    repack_all_kernel<<<(nrep + 255) / 256, 256>>>(w3, w5, w9, wp3, wp5, wp9);

    dim3 cgrid((SS + CTILE - 1) / CTILE, BB);
    conv_kernel<<<cgrid, 256>>>(docs, embed, b3, b5, b9);

    const int smem_bytes = (2 * FF * X_STRIDE + 4 * 16 * P_STRIDE) * 4;
    cudaFuncSetAttribute((const void*)attn_tc_kernel,
                         cudaFuncAttributeMaxDynamicSharedMemorySize, smem_bytes);
    dim3 agrid((LL + LBLK - 1) / LBLK, BB);
    attn_tc_kernel<<<agrid, 128, smem_bytes>>>(wu, leaf, fw, fb, d_y, d_ctx);
}

// round 8
// speedup vs baseline: 1.5036x; 1.5036x over previous
#include <cuda_runtime.h>
#include <cuda_bf16.h>
#include <math.h>
#include <math_constants.h>
#include <stdint.h>

#define BB 8
#define SS 2500
#define EE 128
#define FF 128
#define LL 8921
#define SSB 2504   // bf16 row stride (16B-aligned rows)

// ---------------- device scratch (no allocations allowed) ----------------
__device__ __align__(16) float g_wp3[3 * EE * FF];
__device__ __align__(16) float g_wp5[5 * EE * FF];
__device__ __align__(16) float g_wp9[9 * EE * FF];
// word_features, two layouts (pads absorb cp.async row-tail over-reads):
__device__ __align__(16) uint32_t       g_wfp[(size_t)BB * 64 * SS + 64];   // f-pair packed [b][f/2][s]
__device__ __align__(16) __nv_bfloat16  g_wfs[(size_t)BB * FF * SSB + 64];  // s-contiguous [b][f][s]
__device__ float g_y_fb[BB * LL];
__device__ float g_ctx_fb[(size_t)BB * LL * FF];

__device__ __forceinline__ uint32_t pack_bf16(float lo, float hi) {
    __nv_bfloat162 t = __floats2bfloat162_rn(lo, hi);   // .x = lo (low 16 bits)
    return *reinterpret_cast<uint32_t*>(&t);
}

// ---------------- merged weight repack: [F][E][K] -> [K][E][F] x3 ----------------
__global__ void repack_all_kernel(const float* __restrict__ w3,
                                  const float* __restrict__ w5,
                                  const float* __restrict__ w9,
                                  float* __restrict__ p3,
                                  float* __restrict__ p5,
                                  float* __restrict__ p9) {
    const int n3 = 3 * EE * FF, n5 = 5 * EE * FF, n9 = 9 * EE * FF;
    int idx = blockIdx.x * blockDim.x + threadIdx.x;
    const float* src; float* dst; int K; int loc;
    if (idx < n3)           { src = w3; dst = p3; K = 3; loc = idx; }
    else if (idx < n3 + n5) { src = w5; dst = p5; K = 5; loc = idx - n3; }
    else if (idx < n3 + n5 + n9) { src = w9; dst = p9; K = 9; loc = idx - n3 - n5; }
    else return;
    int kk = loc / (EE * FF);
    int r  = loc % (EE * FF);
    int e  = r / FF;
    int f  = r % FF;
    dst[loc] = src[(f * EE + e) * K + kk];
}

// ================= conv: 4f x 8s per thread, register xs window =================
#define CTILE 64
#define XSTR  72

template <int K>
__device__ __forceinline__ void conv_max2(const float* __restrict__ wp,
                                          const float* __restrict__ bias,
                                          const float (*xs)[XSTR],
                                          int f0, int sg, float mx[4][8]) {
    float acc[4][8];
#pragma unroll
    for (int i = 0; i < 4; i++)
#pragma unroll
        for (int j = 0; j < 8; j++) acc[i][j] = 0.f;

    const int P = K / 2;
    const int w0 = 8 * sg;
#pragma unroll 2
    for (int e = 0; e < EE; e++) {
        float xw[16];
        const float4* xr = (const float4*)(&xs[e][w0]);
        float4 xa = xr[0], xb = xr[1], xc = xr[2], xd = xr[3];
        xw[0]=xa.x; xw[1]=xa.y; xw[2]=xa.z; xw[3]=xa.w;
        xw[4]=xb.x; xw[5]=xb.y; xw[6]=xb.z; xw[7]=xb.w;
        xw[8]=xc.x; xw[9]=xc.y; xw[10]=xc.z; xw[11]=xc.w;
        xw[12]=xd.x; xw[13]=xd.y; xw[14]=xd.z; xw[15]=xd.w;
#pragma unroll
        for (int kk = 0; kk < K; kk++) {
            float4 wv = *(const float4*)(wp + (kk * EE + e) * FF + f0);
            const int off = 4 + kk - P;
#pragma unroll
            for (int j = 0; j < 8; j++) {
                float x = xw[off + j];
                acc[0][j] += wv.x * x;
                acc[1][j] += wv.y * x;
                acc[2][j] += wv.z * x;
                acc[3][j] += wv.w * x;
            }
        }
    }
#pragma unroll
    for (int i = 0; i < 4; i++) {
        float bi = bias[f0 + i];
#pragma unroll
        for (int j = 0; j < 8; j++)
            mx[i][j] = fmaxf(mx[i][j], tanhf(acc[i][j] + bi));
    }
}

__global__ __launch_bounds__(256, 2) void conv_kernel(
    const int* __restrict__ docs, const float* __restrict__ embed,
    const float* __restrict__ b3, const float* __restrict__ b5,
    const float* __restrict__ b9) {
    __shared__ float xs[EE][XSTR];

    int b  = blockIdx.y;
    int s0 = blockIdx.x * CTILE;
    int tid = threadIdx.x, w = tid >> 5, lane = tid & 31;

#pragma unroll
    for (int q = 0; q < 9; q++) {
        int p = w * 9 + q;
        int s = s0 - 4 + p;
        if (s >= 0 && s < SS) {
            int tok = docs[b * SS + s];
            const float* er = embed + (size_t)tok * EE;
            xs[lane      ][p] = er[lane];
            xs[lane + 32][p] = er[lane + 32];
            xs[lane + 64][p] = er[lane + 64];
            xs[lane + 96][p] = er[lane + 96];
        } else {
            xs[lane][p] = 0.f; xs[lane + 32][p] = 0.f;
            xs[lane + 64][p] = 0.f; xs[lane + 96][p] = 0.f;
        }
    }
    __syncthreads();

    int fg = tid >> 3;
    int sg = tid & 7;
    int f0 = fg * 4;

    float mx[4][8];
#pragma unroll
    for (int i = 0; i < 4; i++)
#pragma unroll
        for (int j = 0; j < 8; j++) mx[i][j] = -1e30f;

    conv_max2<3>(g_wp3, b3, xs, f0, sg, mx);
    conv_max2<5>(g_wp5, b5, xs, f0, sg, mx);
    conv_max2<9>(g_wp9, b9, xs, f0, sg, mx);

    // write bf16 word features in both layouts
#pragma unroll
    for (int i = 0; i < 4; i++) {
        __nv_bfloat16* orow = g_wfs + ((size_t)b * FF + f0 + i) * SSB;
#pragma unroll
        for (int j = 0; j < 8; j++) {
            int s = s0 + 8 * sg + j;
            if (s < SS) orow[s] = __float2bfloat16_rn(mx[i][j]);
        }
    }
#pragma unroll
    for (int i2 = 0; i2 < 2; i2++) {
        uint32_t* prow = g_wfp + ((size_t)b * 64 + (f0 >> 1) + i2) * SS;
#pragma unroll
        for (int j = 0; j < 8; j++) {
            int s = s0 + 8 * sg + j;
            if (s < SS) prow[s] = pack_bf16(mx[2 * i2][j], mx[2 * i2 + 1][j]);
        }
    }
}

// ================= bf16 tensor-core label attention (64-wide S tiles) =================
#define LBLK 64
#define XP_STRIDE 68   // u32, f-pair tile [64][68]
#define XS_STRIDE 36   // u32, s-word tile [128][36]
#define PW_STRIDE 36   // u32, per-warp P tile [16][36]
#define STILE     64
#define NT_TILES  ((SS + STILE - 1) / STILE)   // 40

__device__ __forceinline__ void mma_bf16(float (&d)[4],
                                         uint32_t a0, uint32_t a1,
                                         uint32_t a2, uint32_t a3,
                                         uint32_t b0, uint32_t b1) {
    asm volatile(
        "mma.sync.aligned.m16n8k16.row.col.f32.bf16.bf16.f32 "
        "{%0,%1,%2,%3}, {%4,%5,%6,%7}, {%8,%9}, {%0,%1,%2,%3};"
        : "+f"(d[0]), "+f"(d[1]), "+f"(d[2]), "+f"(d[3])
        : "r"(a0), "r"(a1), "r"(a2), "r"(a3), "r"(b0), "r"(b1));
}

__device__ __forceinline__ void ldx_pairs(uint32_t* s_xp, const uint32_t* wpb,
                                          int s0, int tid) {
#pragma unroll
    for (int v = 0; v < 8; v++) {
        int lin = v * 128 + tid;
        int row = lin >> 4, c = lin & 15;      // 64 rows x 16 chunks
        uint32_t dst = (uint32_t)__cvta_generic_to_shared(s_xp + row * XP_STRIDE + c * 4);
        const uint32_t* src = wpb + (size_t)row * SS + s0 + c * 4;
        asm volatile("cp.async.ca.shared.global [%0], [%1], 16;" :: "r"(dst), "l"(src));
    }
}

__device__ __forceinline__ void ldx_sflat(uint32_t* s_xs, const __nv_bfloat16* wsb,
                                          int s0, int tid) {
#pragma unroll
    for (int v = 0; v < 8; v++) {
        int lin = v * 128 + tid;
        int row = lin >> 3, c = lin & 7;       // 128 rows x 8 chunks
        uint32_t dst = (uint32_t)__cvta_generic_to_shared(s_xs + row * XS_STRIDE + c * 4);
        const uint32_t* src = (const uint32_t*)(wsb + (size_t)row * SSB) + (s0 >> 1) + c * 4;
        asm volatile("cp.async.ca.shared.global [%0], [%1], 16;" :: "r"(dst), "l"(src));
    }
}

__global__ __launch_bounds__(128, 2) void attn_tc_kernel(
    const float* __restrict__ wu_w, const int* __restrict__ leaf,
    const float* __restrict__ fw, const float* __restrict__ fb,
    float* __restrict__ y_out, float* __restrict__ ctx_out) {
    extern __shared__ uint32_t sm[];
    uint32_t* s_xp0 = sm;                                   // [64][68]
    uint32_t* s_xs0 = s_xp0 + 64 * XP_STRIDE;               // [128][36]
    uint32_t* s_xp1 = s_xs0 + 128 * XS_STRIDE;
    uint32_t* s_xs1 = s_xp1 + 64 * XP_STRIDE;
    uint32_t* s_p   = s_xs1 + 128 * XS_STRIDE;              // [4][16][36]

    int b   = blockIdx.y;
    int l0  = blockIdx.x * LBLK;
    int tid = threadIdx.x;
    int wid = tid >> 5, lane = tid & 31;
    int q = lane & 3;
    int r = lane >> 2;

    const int lrow = 16 * wid + r;
    int gl0 = l0 + lrow, gl1 = gl0 + 8;
    bool v0 = gl0 < LL, v1 = gl1 < LL;

    // WU A-fragments (bf16 packed) in registers for the whole loop
    const float* wr0 = wu_w + (size_t)(v0 ? leaf[gl0] : 0) * FF;
    const float* wr1 = wu_w + (size_t)(v1 ? leaf[gl1] : 0) * FF;
    uint32_t wua[8][4];
#pragma unroll
    for (int k = 0; k < 8; k++) {
        int k0 = 16 * k;
        wua[k][0] = v0 ? pack_bf16(wr0[k0 + 2 * q],     wr0[k0 + 2 * q + 1]) : 0u;
        wua[k][1] = v1 ? pack_bf16(wr1[k0 + 2 * q],     wr1[k0 + 2 * q + 1]) : 0u;
        wua[k][2] = v0 ? pack_bf16(wr0[k0 + 2 * q + 8], wr0[k0 + 2 * q + 9]) : 0u;
        wua[k][3] = v1 ? pack_bf16(wr1[k0 + 2 * q + 8], wr1[k0 + 2 * q + 9]) : 0u;
    }

    const uint32_t*      wpb = g_wfp + (size_t)b * 64 * SS;
    const __nv_bfloat16* wsb = g_wfs + (size_t)b * FF * SSB;
    uint32_t* s_pw = s_p + wid * 16 * PW_STRIDE;

    float ctx[16][4];
#pragma unroll
    for (int nt = 0; nt < 16; nt++)
#pragma unroll
        for (int c = 0; c < 4; c++) ctx[nt][c] = 0.f;

    float m0 = -CUDART_INF_F, m1 = -CUDART_INF_F;
    float se0 = 0.f, se1 = 0.f;

    ldx_pairs(s_xp0, wpb, 0, tid);
    ldx_sflat(s_xs0, wsb, 0, tid);
    asm volatile("cp.async.commit_group;");

    for (int t = 0; t < NT_TILES; t++) {
        int s0 = t * STILE;
        uint32_t* xp = (t & 1) ? s_xp1 : s_xp0;
        uint32_t* xsf = (t & 1) ? s_xs1 : s_xs0;
        if (t + 1 < NT_TILES) {
            ldx_pairs((t & 1) ? s_xp0 : s_xp1, wpb, s0 + STILE, tid);
            ldx_sflat((t & 1) ? s_xs0 : s_xs1, wsb, s0 + STILE, tid);
            asm volatile("cp.async.commit_group;");
            asm volatile("cp.async.wait_group 1;");
        } else {
            asm volatile("cp.async.wait_group 0;");
        }
        __syncthreads();

        // ---- GEMM1: scores[16 x 64], K=128 in 8 bf16 mma steps ----
        float sc[8][4];
#pragma unroll
        for (int nt = 0; nt < 8; nt++)
#pragma unroll
            for (int c = 0; c < 4; c++) sc[nt][c] = 0.f;

#pragma unroll
        for (int k = 0; k < 8; k++) {
            int fp0 = 8 * k + q;              // f-pair row
#pragma unroll
            for (int nt = 0; nt < 8; nt++) {
                uint32_t b0 = xp[fp0 * XP_STRIDE + 8 * nt + r];
                uint32_t b1 = xp[(fp0 + 4) * XP_STRIDE + 8 * nt + r];
                mma_bf16(sc[nt], wua[k][0], wua[k][1], wua[k][2], wua[k][3], b0, b1);
            }
        }

        // ---- mask tail columns ----
#pragma unroll
        for (int nt = 0; nt < 8; nt++) {
            int s_even = s0 + 8 * nt + 2 * q;
            if (s_even >= SS)     { sc[nt][0] = -CUDART_INF_F; sc[nt][2] = -CUDART_INF_F; }
            if (s_even + 1 >= SS) { sc[nt][1] = -CUDART_INF_F; sc[nt][3] = -CUDART_INF_F; }
        }

        // ---- online softmax over 64 columns ----
        float mx0 = -CUDART_INF_F, mx1 = -CUDART_INF_F;
#pragma unroll
        for (int nt = 0; nt < 8; nt++) {
            mx0 = fmaxf(mx0, fmaxf(sc[nt][0], sc[nt][1]));
            mx1 = fmaxf(mx1, fmaxf(sc[nt][2], sc[nt][3]));
        }
        mx0 = fmaxf(mx0, __shfl_xor_sync(0xffffffffu, mx0, 1));
        mx0 = fmaxf(mx0, __shfl_xor_sync(0xffffffffu, mx0, 2));
        mx1 = fmaxf(mx1, __shfl_xor_sync(0xffffffffu, mx1, 1));
        mx1 = fmaxf(mx1, __shfl_xor_sync(0xffffffffu, mx1, 2));

        float nm0 = fmaxf(m0, mx0), nm1 = fmaxf(m1, mx1);
        float scale0 = __expf(m0 - nm0), scale1 = __expf(m1 - nm1);
        m0 = nm0; m1 = nm1;

        float sum0 = 0.f, sum1 = 0.f;
#pragma unroll
        for (int nt = 0; nt < 8; nt++) {
            float p0 = __expf(sc[nt][0] - m0);
            float p1 = __expf(sc[nt][1] - m0);
            float p2 = __expf(sc[nt][2] - m1);
            float p3 = __expf(sc[nt][3] - m1);
            sum0 += p0 + p1;
            sum1 += p2 + p3;
            int cw = 4 * nt + q;              // packed column word
            s_pw[r * PW_STRIDE + cw]       = pack_bf16(p0, p1);
            s_pw[(r + 8) * PW_STRIDE + cw] = pack_bf16(p2, p3);
        }
        sum0 += __shfl_xor_sync(0xffffffffu, sum0, 1);
        sum0 += __shfl_xor_sync(0xffffffffu, sum0, 2);
        sum1 += __shfl_xor_sync(0xffffffffu, sum1, 1);
        sum1 += __shfl_xor_sync(0xffffffffu, sum1, 2);
        se0 = se0 * scale0 + sum0;
        se1 = se1 * scale1 + sum1;

#pragma unroll
        for (int nt = 0; nt < 16; nt++) {
            ctx[nt][0] *= scale0; ctx[nt][1] *= scale0;
            ctx[nt][2] *= scale1; ctx[nt][3] *= scale1;
        }
        __syncwarp();

        // ---- GEMM2: ctx[16 x 128] += P[16 x 64] @ X^T, 4 bf16 mma steps ----
#pragma unroll
        for (int k = 0; k < 4; k++) {
            int sw = 8 * k + q;               // s-word index
            uint32_t a0 = s_pw[r * PW_STRIDE + sw];
            uint32_t a1 = s_pw[(r + 8) * PW_STRIDE + sw];
            uint32_t a2 = s_pw[r * PW_STRIDE + sw + 4];
            uint32_t a3 = s_pw[(r + 8) * PW_STRIDE + sw + 4];
#pragma unroll
            for (int nt = 0; nt < 16; nt++) {
                uint32_t b0 = xsf[(8 * nt + r) * XS_STRIDE + sw];
                uint32_t b1 = xsf[(8 * nt + r) * XS_STRIDE + sw + 4];
                mma_bf16(ctx[nt], a0, a1, a2, a3, b0, b1);
            }
        }
        __syncthreads();
    }

    // ---- epilogue ----
    float inv0 = 1.f / se0, inv1 = 1.f / se1;
    size_t cb0 = ((size_t)b * LL + gl0) * FF;
    size_t cb1 = ((size_t)b * LL + gl1) * FF;
    float y0 = 0.f, y1 = 0.f;
#pragma unroll
    for (int nt = 0; nt < 16; nt++) {
        int f = 8 * nt + 2 * q;
        if (v0) {
            float c0 = ctx[nt][0] * inv0, c1 = ctx[nt][1] * inv0;
            float2 fwv = *(const float2*)(fw + (size_t)gl0 * FF + f);
            *(float2*)(ctx_out + cb0 + f) = make_float2(c0, c1);
            y0 += c0 * fwv.x + c1 * fwv.y;
        }
        if (v1) {
            float c2 = ctx[nt][2] * inv1, c3 = ctx[nt][3] * inv1;
            float2 fwv = *(const float2*)(fw + (size_t)gl1 * FF + f);
            *(float2*)(ctx_out + cb1 + f) = make_float2(c2, c3);
            y1 += c2 * fwv.x + c3 * fwv.y;
        }
    }
    y0 += __shfl_xor_sync(0xffffffffu, y0, 1);
    y0 += __shfl_xor_sync(0xffffffffu, y0, 2);
    y1 += __shfl_xor_sync(0xffffffffu, y1, 1);
    y1 += __shfl_xor_sync(0xffffffffu, y1, 2);
    if (q == 0 && v0) y_out[(size_t)b * LL + gl0] = y0 + fb[gl0];
    if (q == 0 && v1) y_out[(size_t)b * LL + gl1] = y1 + fb[gl1];
}

// ---------------- launch ----------------
extern "C" void kernel_launch(void* const* d_in, const int* in_sizes, int n_in,
                              void* d_out, int out_size) {
    const int*   docs  = (const int*)  d_in[0];
    const int*   leaf  = (const int*)  d_in[3];
    const float* embed = (const float*)d_in[4];
    const float* wu    = (const float*)d_in[5];
    const float* fw    = (const float*)d_in[6];
    const float* fb    = (const float*)d_in[7];
    const float* w3    = (const float*)d_in[8];
    const float* b3    = (const float*)d_in[9];
    const float* w5    = (const float*)d_in[10];
    const float* b5    = (const float*)d_in[11];
    const float* w9    = (const float*)d_in[12];
    const float* b9    = (const float*)d_in[13];

    const long long NY = (long long)BB * LL;
    const long long NC = (long long)BB * LL * FF;
    float* out = (float*)d_out;
    float* d_y;
    float* d_ctx;
    if ((long long)out_size == NY + NC) {
        d_y = out; d_ctx = out + NY;
    } else if ((long long)out_size == NC) {
        d_ctx = out;
        cudaGetSymbolAddress((void**)&d_y, g_y_fb);
    } else if ((long long)out_size == NY) {
        d_y = out;
        cudaGetSymbolAddress((void**)&d_ctx, g_ctx_fb);
    } else {
        d_y = out; d_ctx = out + NY;
    }

    float* wp3; float* wp5; float* wp9;
    cudaGetSymbolAddress((void**)&wp3, g_wp3);
    cudaGetSymbolAddress((void**)&wp5, g_wp5);
    cudaGetSymbolAddress((void**)&wp9, g_wp9);

    const int nrep = 17 * EE * FF;
    repack_all_kernel<<<(nrep + 255) / 256, 256>>>(w3, w5, w9, wp3, wp5, wp9);

    dim3 cgrid((SS + CTILE - 1) / CTILE, BB);
    conv_kernel<<<cgrid, 256>>>(docs, embed, b3, b5, b9);

    const int smem_bytes = (2 * (64 * XP_STRIDE + 128 * XS_STRIDE) + 4 * 16 * PW_STRIDE) * 4;
    cudaFuncSetAttribute((const void*)attn_tc_kernel,
                         cudaFuncAttributeMaxDynamicSharedMemorySize, smem_bytes);
    dim3 agrid((LL + LBLK - 1) / LBLK, BB);
    attn_tc_kernel<<<agrid, 128, smem_bytes>>>(wu, leaf, fw, fb, d_y, d_ctx);
}

// round 12
// speedup vs baseline: 1.9339x; 1.2862x over previous
#include <cuda_runtime.h>
#include <cuda_bf16.h>
#include <math.h>
#include <math_constants.h>
#include <stdint.h>

#define BB 8
#define SS 2500
#define EE 128
#define FF 128
#define LL 8921
#define SSB 2504   // bf16 row stride (16B-aligned rows)

// ---------------- device scratch (no allocations allowed) ----------------
__device__ __align__(16) float g_wp3[3 * EE * FF];
__device__ __align__(16) float g_wp5[5 * EE * FF];
__device__ __align__(16) float g_wp9[9 * EE * FF];
// word_features, two layouts (pads absorb cp.async row-tail over-reads):
__device__ __align__(16) uint32_t       g_wfp[(size_t)BB * 64 * SS + 64];   // f-pair packed [b][f/2][s]
__device__ __align__(16) __nv_bfloat16  g_wfs[(size_t)BB * FF * SSB + 64];  // s-contiguous [b][f][s]
__device__ float g_y_fb[BB * LL];
__device__ float g_ctx_fb[(size_t)BB * LL * FF];

__device__ __forceinline__ uint32_t pack_bf16(float lo, float hi) {
    __nv_bfloat162 t = __floats2bfloat162_rn(lo, hi);   // .x = lo (low 16 bits)
    return *reinterpret_cast<uint32_t*>(&t);
}
__device__ __forceinline__ uint32_t f2tf32(float v) {
    uint32_t t;
    asm("cvt.rna.tf32.f32 %0, %1;" : "=r"(t) : "f"(v));
    return t;
}
__device__ __forceinline__ float tf32f(float v) {
    return __uint_as_float(f2tf32(v));
}

// ---------------- merged weight repack: [F][E][K] -> [K][E][F] x3, tf32-rounded ----------------
__global__ void repack_all_kernel(const float* __restrict__ w3,
                                  const float* __restrict__ w5,
                                  const float* __restrict__ w9,
                                  float* __restrict__ p3,
                                  float* __restrict__ p5,
                                  float* __restrict__ p9) {
    const int n3 = 3 * EE * FF, n5 = 5 * EE * FF, n9 = 9 * EE * FF;
    int idx = blockIdx.x * blockDim.x + threadIdx.x;
    const float* src; float* dst; int K; int loc;
    if (idx < n3)           { src = w3; dst = p3; K = 3; loc = idx; }
    else if (idx < n3 + n5) { src = w5; dst = p5; K = 5; loc = idx - n3; }
    else if (idx < n3 + n5 + n9) { src = w9; dst = p9; K = 9; loc = idx - n3 - n5; }
    else return;
    int kk = loc / (EE * FF);
    int r  = loc % (EE * FF);
    int e  = r / FF;
    int f  = r % FF;
    dst[loc] = tf32f(src[(f * EE + e) * K + kk]);
}

// ================= conv via tf32 mma: implicit GEMM =================
// block = 256 threads (8 warps). warp w owns f rows [16w, 16w+16); N = 64 s cols.
// K streamed as 68 chunks of 32 (12 for k=3, 20 for k=5, 36 for k=9) with a
// cp.async double-buffered weight tile [32k][128f] (stride 132).
#define CTILE 64
#define XSTR  72       // xs cols: s0-4 .. s0+67
#define WSTR  132      // staged weight tile stride
#define NCH3  12
#define NCH5  20
#define NCH9  36
#define NCHT  (NCH3 + NCH5 + NCH9)   // 68

__device__ __forceinline__ void mma_tf32(float (&d)[4],
                                         uint32_t a0, uint32_t a1,
                                         uint32_t a2, uint32_t a3,
                                         uint32_t b0, uint32_t b1) {
    asm volatile(
        "mma.sync.aligned.m16n8k8.row.col.f32.tf32.tf32.f32 "
        "{%0,%1,%2,%3}, {%4,%5,%6,%7}, {%8,%9}, {%0,%1,%2,%3};"
        : "+f"(d[0]), "+f"(d[1]), "+f"(d[2]), "+f"(d[3])
        : "r"(a0), "r"(a1), "r"(a2), "r"(a3), "r"(b0), "r"(b1));
}

// chunk g -> (weight base ptr for this 32k block, kk, e0, conv id)
__device__ __forceinline__ const float* chunk_src(int g, int& kk, int& e0, int& cid) {
    const float* wp; int c;
    if (g < NCH3)              { wp = g_wp3; c = g;            cid = 0; }
    else if (g < NCH3 + NCH5)  { wp = g_wp5; c = g - NCH3;     cid = 1; }
    else                       { wp = g_wp9; c = g - NCH3 - NCH5; cid = 2; }
    kk = c >> 2;
    e0 = (c & 3) << 5;
    return wp + (size_t)((kk << 7) + e0) * FF;
}

__device__ __forceinline__ void stage_w(float* sbuf, const float* src, int tid) {
#pragma unroll
    for (int v = 0; v < 4; v++) {
        int lin = v * 256 + tid;           // 1024 chunks of 16B
        int row = lin >> 5, c = (lin & 31) * 4;
        uint32_t dst = (uint32_t)__cvta_generic_to_shared(sbuf + row * WSTR + c);
        asm volatile("cp.async.ca.shared.global [%0], [%1], 16;"
                     :: "r"(dst), "l"(src + row * FF + c));
    }
}

__global__ __launch_bounds__(256, 2) void conv_kernel(
    const int* __restrict__ docs, const float* __restrict__ embed,
    const float* __restrict__ b3, const float* __restrict__ b5,
    const float* __restrict__ b9) {
    extern __shared__ float csm[];
    float (*xs)[XSTR] = (float (*)[XSTR])csm;       // [128][72]
    float* swA = csm + EE * XSTR;                    // [32][132]
    float* swB = swA + 32 * WSTR;

    int b  = blockIdx.y;
    int s0 = blockIdx.x * CTILE;
    int tid = threadIdx.x, w = tid >> 5, lane = tid & 31;
    int q = lane & 3;          // 0..3
    int r = lane >> 2;         // 0..7
    const int fbase = 16 * w;

    // prefetch first weight chunk while gathering embeddings
    { int kk, e0, cid; stage_w(swA, chunk_src(0, kk, e0, cid), tid); }
    asm volatile("cp.async.commit_group;");

    // gather 72 embedding rows (tf32-rounded): warp w handles 9 positions
#pragma unroll
    for (int gq = 0; gq < 9; gq++) {
        int p = w * 9 + gq;
        int s = s0 - 4 + p;
        if (s >= 0 && s < SS) {
            int tok = docs[b * SS + s];
            const float* er = embed + (size_t)tok * EE;
            xs[lane      ][p] = tf32f(er[lane]);
            xs[lane + 32][p] = tf32f(er[lane + 32]);
            xs[lane + 64][p] = tf32f(er[lane + 64]);
            xs[lane + 96][p] = tf32f(er[lane + 96]);
        } else {
            xs[lane][p] = 0.f; xs[lane + 32][p] = 0.f;
            xs[lane + 64][p] = 0.f; xs[lane + 96][p] = 0.f;
        }
    }

    float acc[8][4];
    float mx[8][4];
#pragma unroll
    for (int nt = 0; nt < 8; nt++)
#pragma unroll
        for (int c = 0; c < 4; c++) mx[nt][c] = -1e30f;

    const float* biases[3] = {b3, b5, b9};
    const int    Pv[3] = {1, 2, 4};

    for (int g = 0; g < NCHT; g++) {
        int kk, e0, cid;
        chunk_src(g, kk, e0, cid);
        if (g + 1 < NCHT) {
            int kk2, e02, cid2;
            const float* nsrc = chunk_src(g + 1, kk2, e02, cid2);
            stage_w((g & 1) ? swA : swB, nsrc, tid);
            asm volatile("cp.async.commit_group;");
            asm volatile("cp.async.wait_group 1;");
        } else {
            asm volatile("cp.async.wait_group 0;");
        }
        __syncthreads();

        if (g == 0 || g == NCH3 || g == NCH3 + NCH5) {
#pragma unroll
            for (int nt = 0; nt < 8; nt++)
#pragma unroll
                for (int c = 0; c < 4; c++) acc[nt][c] = 0.f;
        }

        const float* sw = (g & 1) ? swB : swA;
        const int off = 4 + kk - Pv[cid];            // xs col shift for this kk
#pragma unroll
        for (int j = 0; j < 4; j++) {
            int krow = 8 * j;
            uint32_t a0 = __float_as_uint(sw[(krow + q) * WSTR + fbase + r]);
            uint32_t a1 = __float_as_uint(sw[(krow + q) * WSTR + fbase + r + 8]);
            uint32_t a2 = __float_as_uint(sw[(krow + q + 4) * WSTR + fbase + r]);
            uint32_t a3 = __float_as_uint(sw[(krow + q + 4) * WSTR + fbase + r + 8]);
            int eb = e0 + krow;
#pragma unroll
            for (int nt = 0; nt < 8; nt++) {
                uint32_t bb0 = __float_as_uint(xs[eb + q][off + 8 * nt + r]);
                uint32_t bb1 = __float_as_uint(xs[eb + q + 4][off + 8 * nt + r]);
                mma_tf32(acc[nt], a0, a1, a2, a3, bb0, bb1);
            }
        }

        // conv-kernel boundary: bias + tanh + running max
        if (g == NCH3 - 1 || g == NCH3 + NCH5 - 1 || g == NCHT - 1) {
            const float* bias = biases[cid];
            float bi0 = __ldg(bias + fbase + r);
            float bi1 = __ldg(bias + fbase + r + 8);
#pragma unroll
            for (int nt = 0; nt < 8; nt++) {
                mx[nt][0] = fmaxf(mx[nt][0], tanhf(acc[nt][0] + bi0));
                mx[nt][1] = fmaxf(mx[nt][1], tanhf(acc[nt][1] + bi0));
                mx[nt][2] = fmaxf(mx[nt][2], tanhf(acc[nt][2] + bi1));
                mx[nt][3] = fmaxf(mx[nt][3], tanhf(acc[nt][3] + bi1));
            }
        }
        __syncthreads();
    }

    // ---- store word features in both layouts ----
    int fr0 = fbase + r, fr1 = fr0 + 8;
    __nv_bfloat16* wsb = g_wfs + (size_t)b * FF * SSB;
    uint32_t*      wpb = g_wfp + (size_t)b * 64 * SS;
#pragma unroll
    for (int nt = 0; nt < 8; nt++) {
        int s = s0 + 8 * nt + 2 * q;        // even; SS even so s<SS covers the pair
        // s-contiguous bf16 layout
        if (s < SS) {
            *(uint32_t*)(wsb + (size_t)fr0 * SSB + s) = pack_bf16(mx[nt][0], mx[nt][1]);
            *(uint32_t*)(wsb + (size_t)fr1 * SSB + s) = pack_bf16(mx[nt][2], mx[nt][3]);
        }
        // f-pair packed layout: partner f+1 lives at lane+4 (r+1, same q)
        float t0 = __shfl_down_sync(0xffffffffu, mx[nt][0], 4);
        float t1 = __shfl_down_sync(0xffffffffu, mx[nt][1], 4);
        float t2 = __shfl_down_sync(0xffffffffu, mx[nt][2], 4);
        float t3 = __shfl_down_sync(0xffffffffu, mx[nt][3], 4);
        if (((r & 1) == 0) && s < SS) {
            int fp0 = fr0 >> 1, fp1 = fr1 >> 1;
            wpb[(size_t)fp0 * SS + s]     = pack_bf16(mx[nt][0], t0);
            wpb[(size_t)fp0 * SS + s + 1] = pack_bf16(mx[nt][1], t1);
            wpb[(size_t)fp1 * SS + s]     = pack_bf16(mx[nt][2], t2);
            wpb[(size_t)fp1 * SS + s + 1] = pack_bf16(mx[nt][3], t3);
        }
    }
}

// ================= bf16 tensor-core label attention (64-wide S tiles) =================
#define LBLK 64
#define XP_STRIDE 68   // u32, f-pair tile [64][68]
#define XS_STRIDE 36   // u32, s-word tile [128][36]
#define PW_STRIDE 36   // u32, per-warp P tile [16][36]
#define STILE     64
#define NT_TILES  ((SS + STILE - 1) / STILE)   // 40

__device__ __forceinline__ void mma_bf16(float (&d)[4],
                                         uint32_t a0, uint32_t a1,
                                         uint32_t a2, uint32_t a3,
                                         uint32_t b0, uint32_t b1) {
    asm volatile(
        "mma.sync.aligned.m16n8k16.row.col.f32.bf16.bf16.f32 "
        "{%0,%1,%2,%3}, {%4,%5,%6,%7}, {%8,%9}, {%0,%1,%2,%3};"
        : "+f"(d[0]), "+f"(d[1]), "+f"(d[2]), "+f"(d[3])
        : "r"(a0), "r"(a1), "r"(a2), "r"(a3), "r"(b0), "r"(b1));
}

__device__ __forceinline__ void ldx_pairs(uint32_t* s_xp, const uint32_t* wpb,
                                          int s0, int tid) {
#pragma unroll
    for (int v = 0; v < 8; v++) {
        int lin = v * 128 + tid;
        int row = lin >> 4, c = lin & 15;
        uint32_t dst = (uint32_t)__cvta_generic_to_shared(s_xp + row * XP_STRIDE + c * 4);
        const uint32_t* src = wpb + (size_t)row * SS + s0 + c * 4;
        asm volatile("cp.async.ca.shared.global [%0], [%1], 16;" :: "r"(dst), "l"(src));
    }
}

__device__ __forceinline__ void ldx_sflat(uint32_t* s_xs, const __nv_bfloat16* wsb,
                                          int s0, int tid) {
#pragma unroll
    for (int v = 0; v < 8; v++) {
        int lin = v * 128 + tid;
        int row = lin >> 3, c = lin & 7;
        uint32_t dst = (uint32_t)__cvta_generic_to_shared(s_xs + row * XS_STRIDE + c * 4);
        const uint32_t* src = (const uint32_t*)(wsb + (size_t)row * SSB) + (s0 >> 1) + c * 4;
        asm volatile("cp.async.ca.shared.global [%0], [%1], 16;" :: "r"(dst), "l"(src));
    }
}

__global__ __launch_bounds__(128, 2) void attn_tc_kernel(
    const float* __restrict__ wu_w, const int* __restrict__ leaf,
    const float* __restrict__ fw, const float* __restrict__ fb,
    float* __restrict__ y_out, float* __restrict__ ctx_out) {
    extern __shared__ uint32_t sm[];
    uint32_t* s_xp0 = sm;
    uint32_t* s_xs0 = s_xp0 + 64 * XP_STRIDE;
    uint32_t* s_xp1 = s_xs0 + 128 * XS_STRIDE;
    uint32_t* s_xs1 = s_xp1 + 64 * XP_STRIDE;
    uint32_t* s_p   = s_xs1 + 128 * XS_STRIDE;

    int b   = blockIdx.y;
    int l0  = blockIdx.x * LBLK;
    int tid = threadIdx.x;
    int wid = tid >> 5, lane = tid & 31;
    int q = lane & 3;
    int r = lane >> 2;

    const int lrow = 16 * wid + r;
    int gl0 = l0 + lrow, gl1 = gl0 + 8;
    bool v0 = gl0 < LL, v1 = gl1 < LL;

    const float* wr0 = wu_w + (size_t)(v0 ? leaf[gl0] : 0) * FF;
    const float* wr1 = wu_w + (size_t)(v1 ? leaf[gl1] : 0) * FF;
    uint32_t wua[8][4];
#pragma unroll
    for (int k = 0; k < 8; k++) {
        int k0 = 16 * k;
        wua[k][0] = v0 ? pack_bf16(wr0[k0 + 2 * q],     wr0[k0 + 2 * q + 1]) : 0u;
        wua[k][1] = v1 ? pack_bf16(wr1[k0 + 2 * q],     wr1[k0 + 2 * q + 1]) : 0u;
        wua[k][2] = v0 ? pack_bf16(wr0[k0 + 2 * q + 8], wr0[k0 + 2 * q + 9]) : 0u;
        wua[k][3] = v1 ? pack_bf16(wr1[k0 + 2 * q + 8], wr1[k0 + 2 * q + 9]) : 0u;
    }

    const uint32_t*      wpb = g_wfp + (size_t)b * 64 * SS;
    const __nv_bfloat16* wsb = g_wfs + (size_t)b * FF * SSB;
    uint32_t* s_pw = s_p + wid * 16 * PW_STRIDE;

    float ctx[16][4];
#pragma unroll
    for (int nt = 0; nt < 16; nt++)
#pragma unroll
        for (int c = 0; c < 4; c++) ctx[nt][c] = 0.f;

    float m0 = -CUDART_INF_F, m1 = -CUDART_INF_F;
    float se0 = 0.f, se1 = 0.f;

    ldx_pairs(s_xp0, wpb, 0, tid);
    ldx_sflat(s_xs0, wsb, 0, tid);
    asm volatile("cp.async.commit_group;");

    for (int t = 0; t < NT_TILES; t++) {
        int s0 = t * STILE;
        uint32_t* xp  = (t & 1) ? s_xp1 : s_xp0;
        uint32_t* xsf = (t & 1) ? s_xs1 : s_xs0;
        if (t + 1 < NT_TILES) {
            ldx_pairs((t & 1) ? s_xp0 : s_xp1, wpb, s0 + STILE, tid);
            ldx_sflat((t & 1) ? s_xs0 : s_xs1, wsb, s0 + STILE, tid);
            asm volatile("cp.async.commit_group;");
            asm volatile("cp.async.wait_group 1;");
        } else {
            asm volatile("cp.async.wait_group 0;");
        }
        __syncthreads();

        float sc[8][4];
#pragma unroll
        for (int nt = 0; nt < 8; nt++)
#pragma unroll
            for (int c = 0; c < 4; c++) sc[nt][c] = 0.f;

#pragma unroll
        for (int k = 0; k < 8; k++) {
            int fp0 = 8 * k + q;
#pragma unroll
            for (int nt = 0; nt < 8; nt++) {
                uint32_t b0 = xp[fp0 * XP_STRIDE + 8 * nt + r];
                uint32_t b1 = xp[(fp0 + 4) * XP_STRIDE + 8 * nt + r];
                mma_bf16(sc[nt], wua[k][0], wua[k][1], wua[k][2], wua[k][3], b0, b1);
            }
        }

#pragma unroll
        for (int nt = 0; nt < 8; nt++) {
            int s_even = s0 + 8 * nt + 2 * q;
            if (s_even >= SS)     { sc[nt][0] = -CUDART_INF_F; sc[nt][2] = -CUDART_INF_F; }
            if (s_even + 1 >= SS) { sc[nt][1] = -CUDART_INF_F; sc[nt][3] = -CUDART_INF_F; }
        }

        float mx0 = -CUDART_INF_F, mx1 = -CUDART_INF_F;
#pragma unroll
        for (int nt = 0; nt < 8; nt++) {
            mx0 = fmaxf(mx0, fmaxf(sc[nt][0], sc[nt][1]));
            mx1 = fmaxf(mx1, fmaxf(sc[nt][2], sc[nt][3]));
        }
        mx0 = fmaxf(mx0, __shfl_xor_sync(0xffffffffu, mx0, 1));
        mx0 = fmaxf(mx0, __shfl_xor_sync(0xffffffffu, mx0, 2));
        mx1 = fmaxf(mx1, __shfl_xor_sync(0xffffffffu, mx1, 1));
        mx1 = fmaxf(mx1, __shfl_xor_sync(0xffffffffu, mx1, 2));

        float nm0 = fmaxf(m0, mx0), nm1 = fmaxf(m1, mx1);
        float scale0 = __expf(m0 - nm0), scale1 = __expf(m1 - nm1);
        m0 = nm0; m1 = nm1;

        float sum0 = 0.f, sum1 = 0.f;
#pragma unroll
        for (int nt = 0; nt < 8; nt++) {
            float p0 = __expf(sc[nt][0] - m0);
            float p1 = __expf(sc[nt][1] - m0);
            float p2 = __expf(sc[nt][2] - m1);
            float p3 = __expf(sc[nt][3] - m1);
            sum0 += p0 + p1;
            sum1 += p2 + p3;
            int cw = 4 * nt + q;
            s_pw[r * PW_STRIDE + cw]       = pack_bf16(p0, p1);
            s_pw[(r + 8) * PW_STRIDE + cw] = pack_bf16(p2, p3);
        }
        sum0 += __shfl_xor_sync(0xffffffffu, sum0, 1);
        sum0 += __shfl_xor_sync(0xffffffffu, sum0, 2);
        sum1 += __shfl_xor_sync(0xffffffffu, sum1, 1);
        sum1 += __shfl_xor_sync(0xffffffffu, sum1, 2);
        se0 = se0 * scale0 + sum0;
        se1 = se1 * scale1 + sum1;

#pragma unroll
        for (int nt = 0; nt < 16; nt++) {
            ctx[nt][0] *= scale0; ctx[nt][1] *= scale0;
            ctx[nt][2] *= scale1; ctx[nt][3] *= scale1;
        }
        __syncwarp();

#pragma unroll
        for (int k = 0; k < 4; k++) {
            int sw = 8 * k + q;
            uint32_t a0 = s_pw[r * PW_STRIDE + sw];
            uint32_t a1 = s_pw[(r + 8) * PW_STRIDE + sw];
            uint32_t a2 = s_pw[r * PW_STRIDE + sw + 4];
            uint32_t a3 = s_pw[(r + 8) * PW_STRIDE + sw + 4];
#pragma unroll
            for (int nt = 0; nt < 16; nt++) {
                uint32_t b0 = xsf[(8 * nt + r) * XS_STRIDE + sw];
                uint32_t b1 = xsf[(8 * nt + r) * XS_STRIDE + sw + 4];
                mma_bf16(ctx[nt], a0, a1, a2, a3, b0, b1);
            }
        }
        __syncthreads();
    }

    float inv0 = 1.f / se0, inv1 = 1.f / se1;
    size_t cb0 = ((size_t)b * LL + gl0) * FF;
    size_t cb1 = ((size_t)b * LL + gl1) * FF;
    float y0 = 0.f, y1 = 0.f;
#pragma unroll
    for (int nt = 0; nt < 16; nt++) {
        int f = 8 * nt + 2 * q;
        if (v0) {
            float c0 = ctx[nt][0] * inv0, c1 = ctx[nt][1] * inv0;
            float2 fwv = *(const float2*)(fw + (size_t)gl0 * FF + f);
            *(float2*)(ctx_out + cb0 + f) = make_float2(c0, c1);
            y0 += c0 * fwv.x + c1 * fwv.y;
        }
        if (v1) {
            float c2 = ctx[nt][2] * inv1, c3 = ctx[nt][3] * inv1;
            float2 fwv = *(const float2*)(fw + (size_t)gl1 * FF + f);
            *(float2*)(ctx_out + cb1 + f) = make_float2(c2, c3);
            y1 += c2 * fwv.x + c3 * fwv.y;
        }
    }
    y0 += __shfl_xor_sync(0xffffffffu, y0, 1);
    y0 += __shfl_xor_sync(0xffffffffu, y0, 2);
    y1 += __shfl_xor_sync(0xffffffffu, y1, 1);
    y1 += __shfl_xor_sync(0xffffffffu, y1, 2);
    if (q == 0 && v0) y_out[(size_t)b * LL + gl0] = y0 + fb[gl0];
    if (q == 0 && v1) y_out[(size_t)b * LL + gl1] = y1 + fb[gl1];
}

// ---------------- launch ----------------
extern "C" void kernel_launch(void* const* d_in, const int* in_sizes, int n_in,
                              void* d_out, int out_size) {
    const int*   docs  = (const int*)  d_in[0];
    const int*   leaf  = (const int*)  d_in[3];
    const float* embed = (const float*)d_in[4];
    const float* wu    = (const float*)d_in[5];
    const float* fw    = (const float*)d_in[6];
    const float* fb    = (const float*)d_in[7];
    const float* w3    = (const float*)d_in[8];
    const float* b3    = (const float*)d_in[9];
    const float* w5    = (const float*)d_in[10];
    const float* b5    = (const float*)d_in[11];
    const float* w9    = (const float*)d_in[12];
    const float* b9    = (const float*)d_in[13];

    const long long NY = (long long)BB * LL;
    const long long NC = (long long)BB * LL * FF;
    float* out = (float*)d_out;
    float* d_y;
    float* d_ctx;
    if ((long long)out_size == NY + NC) {
        d_y = out; d_ctx = out + NY;
    } else if ((long long)out_size == NC) {
        d_ctx = out;
        cudaGetSymbolAddress((void**)&d_y, g_y_fb);
    } else if ((long long)out_size == NY) {
        d_y = out;
        cudaGetSymbolAddress((void**)&d_ctx, g_ctx_fb);
    } else {
        d_y = out; d_ctx = out + NY;
    }

    float* wp3; float* wp5; float* wp9;
    cudaGetSymbolAddress((void**)&wp3, g_wp3);
    cudaGetSymbolAddress((void**)&wp5, g_wp5);
    cudaGetSymbolAddress((void**)&wp9, g_wp9);

    const int nrep = 17 * EE * FF;
    repack_all_kernel<<<(nrep + 255) / 256, 256>>>(w3, w5, w9, wp3, wp5, wp9);

    const int conv_smem = (EE * XSTR + 2 * 32 * WSTR) * 4;   // 70,656 B
    cudaFuncSetAttribute((const void*)conv_kernel,
                         cudaFuncAttributeMaxDynamicSharedMemorySize, conv_smem);
    dim3 cgrid((SS + CTILE - 1) / CTILE, BB);
    conv_kernel<<<cgrid, 256, conv_smem>>>(docs, embed, b3, b5, b9);

    const int smem_bytes = (2 * (64 * XP_STRIDE + 128 * XS_STRIDE) + 4 * 16 * PW_STRIDE) * 4;
    cudaFuncSetAttribute((const void*)attn_tc_kernel,
                         cudaFuncAttributeMaxDynamicSharedMemorySize, smem_bytes);
    dim3 agrid((LL + LBLK - 1) / LBLK, BB);
    attn_tc_kernel<<<agrid, 128, smem_bytes>>>(wu, leaf, fw, fb, d_y, d_ctx);
}

// round 13
// speedup vs baseline: 2.1158x; 1.0940x over previous
#include <cuda_runtime.h>
#include <cuda_bf16.h>
#include <math.h>
#include <math_constants.h>
#include <stdint.h>

#define BB 8
#define SS 2500
#define EE 128
#define FF 128
#define LL 8921
#define SSB 2504   // bf16 row stride (16B-aligned rows)

// ---------------- device scratch (no allocations allowed) ----------------
__device__ __align__(16) float g_wp3[3 * EE * FF];
__device__ __align__(16) float g_wp5[5 * EE * FF];
__device__ __align__(16) float g_wp9[9 * EE * FF];
// word_features, two layouts (pads absorb cp.async row-tail over-reads):
__device__ __align__(16) uint32_t       g_wfp[(size_t)BB * 64 * SS + 64];   // f-pair packed [b][f/2][s]
__device__ __align__(16) __nv_bfloat16  g_wfs[(size_t)BB * FF * SSB + 64];  // s-contiguous [b][f][s]
__device__ float g_y_fb[BB * LL];
__device__ float g_ctx_fb[(size_t)BB * LL * FF];

__device__ __forceinline__ uint32_t pack_bf16(float lo, float hi) {
    __nv_bfloat162 t = __floats2bfloat162_rn(lo, hi);   // .x = lo (low 16 bits)
    return *reinterpret_cast<uint32_t*>(&t);
}
__device__ __forceinline__ uint32_t f2tf32(float v) {
    uint32_t t;
    asm("cvt.rna.tf32.f32 %0, %1;" : "=r"(t) : "f"(v));
    return t;
}
__device__ __forceinline__ float tf32f(float v) {
    return __uint_as_float(f2tf32(v));
}

// ---------------- merged weight repack: [F][E][K] -> [K][E][F] x3, tf32-rounded ----------------
__global__ void repack_all_kernel(const float* __restrict__ w3,
                                  const float* __restrict__ w5,
                                  const float* __restrict__ w9,
                                  float* __restrict__ p3,
                                  float* __restrict__ p5,
                                  float* __restrict__ p9) {
    const int n3 = 3 * EE * FF, n5 = 5 * EE * FF, n9 = 9 * EE * FF;
    int idx = blockIdx.x * blockDim.x + threadIdx.x;
    const float* src; float* dst; int K; int loc;
    if (idx < n3)           { src = w3; dst = p3; K = 3; loc = idx; }
    else if (idx < n3 + n5) { src = w5; dst = p5; K = 5; loc = idx - n3; }
    else if (idx < n3 + n5 + n9) { src = w9; dst = p9; K = 9; loc = idx - n3 - n5; }
    else return;
    int kk = loc / (EE * FF);
    int r  = loc % (EE * FF);
    int e  = r / FF;
    int f  = r % FF;
    dst[loc] = tf32f(src[(f * EE + e) * K + kk]);
}

// ================= conv via tf32 mma: implicit GEMM =================
#define CTILE 64
#define XSTR  72       // xs cols: s0-4 .. s0+67
#define WSTR  132      // staged weight tile stride
#define NCH3  12
#define NCH5  20
#define NCH9  36
#define NCHT  (NCH3 + NCH5 + NCH9)   // 68

__device__ __forceinline__ void mma_tf32(float (&d)[4],
                                         uint32_t a0, uint32_t a1,
                                         uint32_t a2, uint32_t a3,
                                         uint32_t b0, uint32_t b1) {
    asm volatile(
        "mma.sync.aligned.m16n8k8.row.col.f32.tf32.tf32.f32 "
        "{%0,%1,%2,%3}, {%4,%5,%6,%7}, {%8,%9}, {%0,%1,%2,%3};"
        : "+f"(d[0]), "+f"(d[1]), "+f"(d[2]), "+f"(d[3])
        : "r"(a0), "r"(a1), "r"(a2), "r"(a3), "r"(b0), "r"(b1));
}

__device__ __forceinline__ const float* chunk_src(int g, int& kk, int& e0, int& cid) {
    const float* wp; int c;
    if (g < NCH3)              { wp = g_wp3; c = g;            cid = 0; }
    else if (g < NCH3 + NCH5)  { wp = g_wp5; c = g - NCH3;     cid = 1; }
    else                       { wp = g_wp9; c = g - NCH3 - NCH5; cid = 2; }
    kk = c >> 2;
    e0 = (c & 3) << 5;
    return wp + (size_t)((kk << 7) + e0) * FF;
}

__device__ __forceinline__ void stage_w(float* sbuf, const float* src, int tid) {
#pragma unroll
    for (int v = 0; v < 4; v++) {
        int lin = v * 256 + tid;
        int row = lin >> 5, c = (lin & 31) * 4;
        uint32_t dst = (uint32_t)__cvta_generic_to_shared(sbuf + row * WSTR + c);
        asm volatile("cp.async.ca.shared.global [%0], [%1], 16;"
                     :: "r"(dst), "l"(src + row * FF + c));
    }
}

__global__ __launch_bounds__(256, 2) void conv_kernel(
    const int* __restrict__ docs, const float* __restrict__ embed,
    const float* __restrict__ b3, const float* __restrict__ b5,
    const float* __restrict__ b9) {
    extern __shared__ float csm[];
    float (*xs)[XSTR] = (float (*)[XSTR])csm;       // [128][72]
    float* swA = csm + EE * XSTR;                    // [32][132]
    float* swB = swA + 32 * WSTR;

    int b  = blockIdx.y;
    int s0 = blockIdx.x * CTILE;
    int tid = threadIdx.x, w = tid >> 5, lane = tid & 31;
    int q = lane & 3;
    int r = lane >> 2;
    const int fbase = 16 * w;

    { int kk, e0, cid; stage_w(swA, chunk_src(0, kk, e0, cid), tid); }
    asm volatile("cp.async.commit_group;");

#pragma unroll
    for (int gq = 0; gq < 9; gq++) {
        int p = w * 9 + gq;
        int s = s0 - 4 + p;
        if (s >= 0 && s < SS) {
            int tok = docs[b * SS + s];
            const float* er = embed + (size_t)tok * EE;
            xs[lane      ][p] = tf32f(er[lane]);
            xs[lane + 32][p] = tf32f(er[lane + 32]);
            xs[lane + 64][p] = tf32f(er[lane + 64]);
            xs[lane + 96][p] = tf32f(er[lane + 96]);
        } else {
            xs[lane][p] = 0.f; xs[lane + 32][p] = 0.f;
            xs[lane + 64][p] = 0.f; xs[lane + 96][p] = 0.f;
        }
    }

    float acc[8][4];
    float mx[8][4];
#pragma unroll
    for (int nt = 0; nt < 8; nt++)
#pragma unroll
        for (int c = 0; c < 4; c++) mx[nt][c] = -1e30f;

    const float* biases[3] = {b3, b5, b9};
    const int    Pv[3] = {1, 2, 4};

    for (int g = 0; g < NCHT; g++) {
        int kk, e0, cid;
        chunk_src(g, kk, e0, cid);
        if (g + 1 < NCHT) {
            int kk2, e02, cid2;
            const float* nsrc = chunk_src(g + 1, kk2, e02, cid2);
            stage_w((g & 1) ? swA : swB, nsrc, tid);
            asm volatile("cp.async.commit_group;");
            asm volatile("cp.async.wait_group 1;");
        } else {
            asm volatile("cp.async.wait_group 0;");
        }
        __syncthreads();

        if (g == 0 || g == NCH3 || g == NCH3 + NCH5) {
#pragma unroll
            for (int nt = 0; nt < 8; nt++)
#pragma unroll
                for (int c = 0; c < 4; c++) acc[nt][c] = 0.f;
        }

        const float* sw = (g & 1) ? swB : swA;
        const int off = 4 + kk - Pv[cid];
#pragma unroll
        for (int j = 0; j < 4; j++) {
            int krow = 8 * j;
            uint32_t a0 = __float_as_uint(sw[(krow + q) * WSTR + fbase + r]);
            uint32_t a1 = __float_as_uint(sw[(krow + q) * WSTR + fbase + r + 8]);
            uint32_t a2 = __float_as_uint(sw[(krow + q + 4) * WSTR + fbase + r]);
            uint32_t a3 = __float_as_uint(sw[(krow + q + 4) * WSTR + fbase + r + 8]);
            int eb = e0 + krow;
#pragma unroll
            for (int nt = 0; nt < 8; nt++) {
                uint32_t bb0 = __float_as_uint(xs[eb + q][off + 8 * nt + r]);
                uint32_t bb1 = __float_as_uint(xs[eb + q + 4][off + 8 * nt + r]);
                mma_tf32(acc[nt], a0, a1, a2, a3, bb0, bb1);
            }
        }

        if (g == NCH3 - 1 || g == NCH3 + NCH5 - 1 || g == NCHT - 1) {
            const float* bias = biases[cid];
            float bi0 = __ldg(bias + fbase + r);
            float bi1 = __ldg(bias + fbase + r + 8);
#pragma unroll
            for (int nt = 0; nt < 8; nt++) {
                mx[nt][0] = fmaxf(mx[nt][0], tanhf(acc[nt][0] + bi0));
                mx[nt][1] = fmaxf(mx[nt][1], tanhf(acc[nt][1] + bi0));
                mx[nt][2] = fmaxf(mx[nt][2], tanhf(acc[nt][2] + bi1));
                mx[nt][3] = fmaxf(mx[nt][3], tanhf(acc[nt][3] + bi1));
            }
        }
        __syncthreads();
    }

    int fr0 = fbase + r, fr1 = fr0 + 8;
    __nv_bfloat16* wsb = g_wfs + (size_t)b * FF * SSB;
    uint32_t*      wpb = g_wfp + (size_t)b * 64 * SS;
#pragma unroll
    for (int nt = 0; nt < 8; nt++) {
        int s = s0 + 8 * nt + 2 * q;
        if (s < SS) {
            *(uint32_t*)(wsb + (size_t)fr0 * SSB + s) = pack_bf16(mx[nt][0], mx[nt][1]);
            *(uint32_t*)(wsb + (size_t)fr1 * SSB + s) = pack_bf16(mx[nt][2], mx[nt][3]);
        }
        float t0 = __shfl_down_sync(0xffffffffu, mx[nt][0], 4);
        float t1 = __shfl_down_sync(0xffffffffu, mx[nt][1], 4);
        float t2 = __shfl_down_sync(0xffffffffu, mx[nt][2], 4);
        float t3 = __shfl_down_sync(0xffffffffu, mx[nt][3], 4);
        if (((r & 1) == 0) && s < SS) {
            int fp0 = fr0 >> 1, fp1 = fr1 >> 1;
            wpb[(size_t)fp0 * SS + s]     = pack_bf16(mx[nt][0], t0);
            wpb[(size_t)fp0 * SS + s + 1] = pack_bf16(mx[nt][1], t1);
            wpb[(size_t)fp1 * SS + s]     = pack_bf16(mx[nt][2], t2);
            wpb[(size_t)fp1 * SS + s + 1] = pack_bf16(mx[nt][3], t3);
        }
    }
}

// ================= bf16 tensor-core label attention v4 =================
// No online max (scores provably small: |wu.wf| <~ 5, exp overflow-free;
// softmax is shift-invariant so the result is mathematically identical).
// P stays in registers: GEMM1's C-fragment layout == GEMM2's A-fragment layout.
#define LBLK 64
#define XP_STRIDE 68   // u32, f-pair tile [64][68]
#define XS_STRIDE 36   // u32, s-word tile [128][36]
#define STILE     64
#define NT_TILES  ((SS + STILE - 1) / STILE)   // 40

__device__ __forceinline__ void mma_bf16(float (&d)[4],
                                         uint32_t a0, uint32_t a1,
                                         uint32_t a2, uint32_t a3,
                                         uint32_t b0, uint32_t b1) {
    asm volatile(
        "mma.sync.aligned.m16n8k16.row.col.f32.bf16.bf16.f32 "
        "{%0,%1,%2,%3}, {%4,%5,%6,%7}, {%8,%9}, {%0,%1,%2,%3};"
        : "+f"(d[0]), "+f"(d[1]), "+f"(d[2]), "+f"(d[3])
        : "r"(a0), "r"(a1), "r"(a2), "r"(a3), "r"(b0), "r"(b1));
}

__device__ __forceinline__ void ldx_pairs(uint32_t* s_xp, const uint32_t* wpb,
                                          int s0, int tid) {
#pragma unroll
    for (int v = 0; v < 8; v++) {
        int lin = v * 128 + tid;
        int row = lin >> 4, c = lin & 15;
        uint32_t dst = (uint32_t)__cvta_generic_to_shared(s_xp + row * XP_STRIDE + c * 4);
        const uint32_t* src = wpb + (size_t)row * SS + s0 + c * 4;
        asm volatile("cp.async.ca.shared.global [%0], [%1], 16;" :: "r"(dst), "l"(src));
    }
}

__device__ __forceinline__ void ldx_sflat(uint32_t* s_xs, const __nv_bfloat16* wsb,
                                          int s0, int tid) {
#pragma unroll
    for (int v = 0; v < 8; v++) {
        int lin = v * 128 + tid;
        int row = lin >> 3, c = lin & 7;
        uint32_t dst = (uint32_t)__cvta_generic_to_shared(s_xs + row * XS_STRIDE + c * 4);
        const uint32_t* src = (const uint32_t*)(wsb + (size_t)row * SSB) + (s0 >> 1) + c * 4;
        asm volatile("cp.async.ca.shared.global [%0], [%1], 16;" :: "r"(dst), "l"(src));
    }
}

__global__ __launch_bounds__(128, 2) void attn_tc_kernel(
    const float* __restrict__ wu_w, const int* __restrict__ leaf,
    const float* __restrict__ fw, const float* __restrict__ fb,
    float* __restrict__ y_out, float* __restrict__ ctx_out) {
    extern __shared__ uint32_t sm[];
    uint32_t* s_xp0 = sm;
    uint32_t* s_xs0 = s_xp0 + 64 * XP_STRIDE;
    uint32_t* s_xp1 = s_xs0 + 128 * XS_STRIDE;
    uint32_t* s_xs1 = s_xp1 + 64 * XP_STRIDE;

    int b   = blockIdx.y;
    int l0  = blockIdx.x * LBLK;
    int tid = threadIdx.x;
    int wid = tid >> 5, lane = tid & 31;
    int q = lane & 3;
    int r = lane >> 2;

    const int lrow = 16 * wid + r;
    int gl0 = l0 + lrow, gl1 = gl0 + 8;
    bool v0 = gl0 < LL, v1 = gl1 < LL;

    const float* wr0 = wu_w + (size_t)(v0 ? leaf[gl0] : 0) * FF;
    const float* wr1 = wu_w + (size_t)(v1 ? leaf[gl1] : 0) * FF;
    uint32_t wua[8][4];
#pragma unroll
    for (int k = 0; k < 8; k++) {
        int k0 = 16 * k;
        wua[k][0] = v0 ? pack_bf16(wr0[k0 + 2 * q],     wr0[k0 + 2 * q + 1]) : 0u;
        wua[k][1] = v1 ? pack_bf16(wr1[k0 + 2 * q],     wr1[k0 + 2 * q + 1]) : 0u;
        wua[k][2] = v0 ? pack_bf16(wr0[k0 + 2 * q + 8], wr0[k0 + 2 * q + 9]) : 0u;
        wua[k][3] = v1 ? pack_bf16(wr1[k0 + 2 * q + 8], wr1[k0 + 2 * q + 9]) : 0u;
    }

    const uint32_t*      wpb = g_wfp + (size_t)b * 64 * SS;
    const __nv_bfloat16* wsb = g_wfs + (size_t)b * FF * SSB;

    float ctx[16][4];
#pragma unroll
    for (int nt = 0; nt < 16; nt++)
#pragma unroll
        for (int c = 0; c < 4; c++) ctx[nt][c] = 0.f;

    float psum0 = 0.f, psum1 = 0.f;   // per-thread partial softmax denominators

    ldx_pairs(s_xp0, wpb, 0, tid);
    ldx_sflat(s_xs0, wsb, 0, tid);
    asm volatile("cp.async.commit_group;");

    for (int t = 0; t < NT_TILES; t++) {
        int s0 = t * STILE;
        uint32_t* xp  = (t & 1) ? s_xp1 : s_xp0;
        uint32_t* xsf = (t & 1) ? s_xs1 : s_xs0;
        if (t + 1 < NT_TILES) {
            ldx_pairs((t & 1) ? s_xp0 : s_xp1, wpb, s0 + STILE, tid);
            ldx_sflat((t & 1) ? s_xs0 : s_xs1, wsb, s0 + STILE, tid);
            asm volatile("cp.async.commit_group;");
            asm volatile("cp.async.wait_group 1;");
        } else {
            asm volatile("cp.async.wait_group 0;");
        }
        __syncthreads();

        // ---- GEMM1: scores[16 x 64] ----
        float sc[8][4];
#pragma unroll
        for (int nt = 0; nt < 8; nt++)
#pragma unroll
            for (int c = 0; c < 4; c++) sc[nt][c] = 0.f;

#pragma unroll
        for (int k = 0; k < 8; k++) {
            int fp0 = 8 * k + q;
#pragma unroll
            for (int nt = 0; nt < 8; nt++) {
                uint32_t b0 = xp[fp0 * XP_STRIDE + 8 * nt + r];
                uint32_t b1 = xp[(fp0 + 4) * XP_STRIDE + 8 * nt + r];
                mma_bf16(sc[nt], wua[k][0], wua[k][1], wua[k][2], wua[k][3], b0, b1);
            }
        }

        // ---- tail mask (only final tile has s >= SS) ----
        if (t == NT_TILES - 1) {
#pragma unroll
            for (int nt = 0; nt < 8; nt++) {
                int s_even = s0 + 8 * nt + 2 * q;
                if (s_even >= SS)     { sc[nt][0] = -CUDART_INF_F; sc[nt][2] = -CUDART_INF_F; }
                if (s_even + 1 >= SS) { sc[nt][1] = -CUDART_INF_F; sc[nt][3] = -CUDART_INF_F; }
            }
        }

        // ---- exp (no max subtraction) + pack P into A-fragment registers ----
        uint32_t pp[8][2];
#pragma unroll
        for (int nt = 0; nt < 8; nt++) {
            float p0 = __expf(sc[nt][0]);
            float p1 = __expf(sc[nt][1]);
            float p2 = __expf(sc[nt][2]);
            float p3 = __expf(sc[nt][3]);
            psum0 += p0 + p1;
            psum1 += p2 + p3;
            pp[nt][0] = pack_bf16(p0, p1);   // row r    (labels lrow)
            pp[nt][1] = pack_bf16(p2, p3);   // row r+8  (labels lrow+8)
        }

        // ---- GEMM2: ctx[16 x 128] += P[16 x 64] @ X^T (P from registers) ----
#pragma unroll
        for (int kc = 0; kc < 4; kc++) {
            uint32_t a0 = pp[2 * kc][0];
            uint32_t a1 = pp[2 * kc][1];
            uint32_t a2 = pp[2 * kc + 1][0];
            uint32_t a3 = pp[2 * kc + 1][1];
            int sw = 8 * kc + q;
#pragma unroll
            for (int nt = 0; nt < 16; nt++) {
                uint32_t b0 = xsf[(8 * nt + r) * XS_STRIDE + sw];
                uint32_t b1 = xsf[(8 * nt + r) * XS_STRIDE + sw + 4];
                mma_bf16(ctx[nt], a0, a1, a2, a3, b0, b1);
            }
        }
        __syncthreads();
    }

    // ---- epilogue: reduce denominators once, normalize, write, fused y ----
    float se0 = psum0, se1 = psum1;
    se0 += __shfl_xor_sync(0xffffffffu, se0, 1);
    se0 += __shfl_xor_sync(0xffffffffu, se0, 2);
    se1 += __shfl_xor_sync(0xffffffffu, se1, 1);
    se1 += __shfl_xor_sync(0xffffffffu, se1, 2);

    float inv0 = 1.f / se0, inv1 = 1.f / se1;
    size_t cb0 = ((size_t)b * LL + gl0) * FF;
    size_t cb1 = ((size_t)b * LL + gl1) * FF;
    float y0 = 0.f, y1 = 0.f;
#pragma unroll
    for (int nt = 0; nt < 16; nt++) {
        int f = 8 * nt + 2 * q;
        if (v0) {
            float c0 = ctx[nt][0] * inv0, c1 = ctx[nt][1] * inv0;
            float2 fwv = *(const float2*)(fw + (size_t)gl0 * FF + f);
            *(float2*)(ctx_out + cb0 + f) = make_float2(c0, c1);
            y0 += c0 * fwv.x + c1 * fwv.y;
        }
        if (v1) {
            float c2 = ctx[nt][2] * inv1, c3 = ctx[nt][3] * inv1;
            float2 fwv = *(const float2*)(fw + (size_t)gl1 * FF + f);
            *(float2*)(ctx_out + cb1 + f) = make_float2(c2, c3);
            y1 += c2 * fwv.x + c3 * fwv.y;
        }
    }
    y0 += __shfl_xor_sync(0xffffffffu, y0, 1);
    y0 += __shfl_xor_sync(0xffffffffu, y0, 2);
    y1 += __shfl_xor_sync(0xffffffffu, y1, 1);
    y1 += __shfl_xor_sync(0xffffffffu, y1, 2);
    if (q == 0 && v0) y_out[(size_t)b * LL + gl0] = y0 + fb[gl0];
    if (q == 0 && v1) y_out[(size_t)b * LL + gl1] = y1 + fb[gl1];
}

// ---------------- launch ----------------
extern "C" void kernel_launch(void* const* d_in, const int* in_sizes, int n_in,
                              void* d_out, int out_size) {
    const int*   docs  = (const int*)  d_in[0];
    const int*   leaf  = (const int*)  d_in[3];
    const float* embed = (const float*)d_in[4];
    const float* wu    = (const float*)d_in[5];
    const float* fw    = (const float*)d_in[6];
    const float* fb    = (const float*)d_in[7];
    const float* w3    = (const float*)d_in[8];
    const float* b3    = (const float*)d_in[9];
    const float* w5    = (const float*)d_in[10];
    const float* b5    = (const float*)d_in[11];
    const float* w9    = (const float*)d_in[12];
    const float* b9    = (const float*)d_in[13];

    const long long NY = (long long)BB * LL;
    const long long NC = (long long)BB * LL * FF;
    float* out = (float*)d_out;
    float* d_y;
    float* d_ctx;
    if ((long long)out_size == NY + NC) {
        d_y = out; d_ctx = out + NY;
    } else if ((long long)out_size == NC) {
        d_ctx = out;
        cudaGetSymbolAddress((void**)&d_y, g_y_fb);
    } else if ((long long)out_size == NY) {
        d_y = out;
        cudaGetSymbolAddress((void**)&d_ctx, g_ctx_fb);
    } else {
        d_y = out; d_ctx = out + NY;
    }

    float* wp3; float* wp5; float* wp9;
    cudaGetSymbolAddress((void**)&wp3, g_wp3);
    cudaGetSymbolAddress((void**)&wp5, g_wp5);
    cudaGetSymbolAddress((void**)&wp9, g_wp9);

    const int nrep = 17 * EE * FF;
    repack_all_kernel<<<(nrep + 255) / 256, 256>>>(w3, w5, w9, wp3, wp5, wp9);

    const int conv_smem = (EE * XSTR + 2 * 32 * WSTR) * 4;   // 70,656 B
    cudaFuncSetAttribute((const void*)conv_kernel,
                         cudaFuncAttributeMaxDynamicSharedMemorySize, conv_smem);
    dim3 cgrid((SS + CTILE - 1) / CTILE, BB);
    conv_kernel<<<cgrid, 256, conv_smem>>>(docs, embed, b3, b5, b9);

    const int smem_bytes = (2 * (64 * XP_STRIDE + 128 * XS_STRIDE)) * 4;  // 71,680 B
    cudaFuncSetAttribute((const void*)attn_tc_kernel,
                         cudaFuncAttributeMaxDynamicSharedMemorySize, smem_bytes);
    dim3 agrid((LL + LBLK - 1) / LBLK, BB);
    attn_tc_kernel<<<agrid, 128, smem_bytes>>>(wu, leaf, fw, fb, d_y, d_ctx);
}